// round 7
// baseline (speedup 1.0000x reference)
#include <cuda_runtime.h>
#include <cuda_bf16.h>
#include <math.h>
#include <stdint.h>

#define DIM    3072
#define NHEADS 24
#define HDIM   128
#define SEQ    2304

// ---------------------------------------------------------------------------
// Scratch (allocation-free: __device__ globals)
// ---------------------------------------------------------------------------
__device__ float g_q[SEQ * DIM];
__device__ float g_k[SEQ * DIM];
__device__ float g_v[SEQ * DIM];

__device__ __nv_bfloat16 g_xh[SEQ * DIM],  g_xl[SEQ * DIM];
__device__ __nv_bfloat16 g_ah[SEQ * DIM],  g_al[SEQ * DIM];
__device__ __nv_bfloat16 g_qh[SEQ * DIM],  g_ql[SEQ * DIM];
__device__ __nv_bfloat16 g_kh[SEQ * DIM],  g_kl[SEQ * DIM];
__device__ __nv_bfloat16 g_vh[SEQ * DIM],  g_vl[SEQ * DIM];
__device__ __nv_bfloat16 g_wqh[DIM * DIM], g_wql[DIM * DIM];
__device__ __nv_bfloat16 g_wkh[DIM * DIM], g_wkl[DIM * DIM];
__device__ __nv_bfloat16 g_wvh[DIM * DIM], g_wvl[DIM * DIM];
__device__ __nv_bfloat16 g_woh[DIM * DIM], g_wol[DIM * DIM];

// fp32 pair -> packed bf16 hi / bf16 lo
__device__ __forceinline__ uint2 split2(float a, float b) {
    __nv_bfloat162 h = __floats2bfloat162_rn(a, b);
    __nv_bfloat162 l = __floats2bfloat162_rn(a - __bfloat162float(h.x),
                                             b - __bfloat162float(h.y));
    uint2 r;
    r.x = *reinterpret_cast<uint32_t*>(&h);
    r.y = *reinterpret_cast<uint32_t*>(&l);
    return r;
}

__device__ __forceinline__ void cp16(uint32_t saddr, const void* gptr) {
    asm volatile("cp.async.cg.shared.global [%0], [%1], 16;"
                 :: "r"(saddr), "l"(gptr));
}

__device__ __forceinline__ void ldmx4(uint32_t& r0, uint32_t& r1,
                                      uint32_t& r2, uint32_t& r3, uint32_t addr) {
    asm volatile("ldmatrix.sync.aligned.m8n8.x4.shared.b16 {%0,%1,%2,%3}, [%4];"
                 : "=r"(r0), "=r"(r1), "=r"(r2), "=r"(r3) : "r"(addr));
}

#define MMA_BF16(d, a, b)                                                     \
    asm volatile("mma.sync.aligned.m16n8k16.row.col.f32.bf16.bf16.f32 "       \
                 "{%0,%1,%2,%3}, {%4,%5,%6,%7}, {%8,%9}, {%0,%1,%2,%3};"      \
                 : "+f"(d[0]), "+f"(d[1]), "+f"(d[2]), "+f"(d[3])             \
                 : "r"(a[0]), "r"(a[1]), "r"(a[2]), "r"(a[3]),                \
                   "r"(b[0]), "r"(b[1]))

// ---------------------------------------------------------------------------
// fp32 -> (bf16 hi, bf16 lo) split.
// ---------------------------------------------------------------------------
__global__ __launch_bounds__(256)
void split_f32(const float* __restrict__ in, __nv_bfloat16* __restrict__ hi,
               __nv_bfloat16* __restrict__ lo, int n) {
    int i = (blockIdx.x * 256 + threadIdx.x) * 4;
    if (i + 3 >= n) return;
    float4 v = *(const float4*)(in + i);
    uint2 p0 = split2(v.x, v.y);
    uint2 p1 = split2(v.z, v.w);
    *(uint2*)(hi + i) = make_uint2(p0.x, p1.x);
    *(uint2*)(lo + i) = make_uint2(p0.y, p1.y);
}

// ---------------------------------------------------------------------------
// bf16x3 GEMM (NT), cp.async 2-stage pipeline, ldmatrix fragments, batched z.
// BM=BN=128, BK=32, 256 threads = 8 warps (2M x 4N), warp tile 64x32.
// ---------------------------------------------------------------------------
#define SSTR 20                       // u32 per smem row (16 data + 4 pad)
#define ARR_BYTES  (128 * SSTR * 4)   // 10240
#define STG_BYTES  (4 * ARR_BYTES)    // 40960
#define STG_U32    (STG_BYTES / 4)

struct GemmBatch {
    const __nv_bfloat16* Bh[3];
    const __nv_bfloat16* Bl[3];
    const float*         bias[3];
    float*               C[3];
};

__global__ __launch_bounds__(256)
void gemm_bf16x3_pipe(const __nv_bfloat16* __restrict__ Ah,
                      const __nv_bfloat16* __restrict__ Al,
                      GemmBatch batch, int M, int N, int K) {
    extern __shared__ uint32_t smem[];
    const uint32_t sbase = (uint32_t)__cvta_generic_to_shared(smem);

    const __nv_bfloat16* __restrict__ Bh = batch.Bh[blockIdx.z];
    const __nv_bfloat16* __restrict__ Bl = batch.Bl[blockIdx.z];
    const float* __restrict__ bias = batch.bias[blockIdx.z];
    float* __restrict__ C = batch.C[blockIdx.z];

    const int bm = blockIdx.y * 128, bn = blockIdx.x * 128;
    const int tid = threadIdx.x;
    const int w = tid >> 5, lane = tid & 31;
    const int wm = w & 1, wn = w >> 1;
    const int g = lane >> 2, tg = lane & 3;

    // ldmatrix byte offsets (within one array, stage-independent)
    uint32_t offA[4], offB[2];
#pragma unroll
    for (int mi = 0; mi < 4; mi++)
        offA[mi] = ((wm * 64 + mi * 16 + (lane & 15)) * SSTR +
                    ((lane >> 4) << 2)) * 4;
#pragma unroll
    for (int ni2 = 0; ni2 < 2; ni2++)
        offB[ni2] = ((wn * 32 + ni2 * 16 + (lane & 7) + ((lane >> 4) << 3)) * SSTR +
                     (((lane >> 3) & 1) << 2)) * 4;

    // loader mapping: 512 16B-chunks per array per stage, 2 per thread
    const int r0 = tid >> 2,          q0 = tid & 3;
    const int r1 = (tid + 256) >> 2,  q1 = (tid + 256) & 3;

    float acc[4][4][4];
#pragma unroll
    for (int mi = 0; mi < 4; mi++)
#pragma unroll
        for (int ni = 0; ni < 4; ni++)
#pragma unroll
            for (int r = 0; r < 4; r++) acc[mi][ni][r] = 0.f;

    auto issue = [&](int kt, int stage) {
        const uint32_t sb = sbase + (uint32_t)stage * STG_BYTES;
        const uint32_t oA0 = (r0 * SSTR + q0 * 4) * 4;
        const uint32_t oA1 = (r1 * SSTR + q1 * 4) * 4;
        const size_t ga0 = (size_t)(bm + r0) * K + kt + q0 * 8;
        const size_t ga1 = (size_t)(bm + r1) * K + kt + q1 * 8;
        const size_t gb0 = (size_t)(bn + r0) * K + kt + q0 * 8;
        const size_t gb1 = (size_t)(bn + r1) * K + kt + q1 * 8;
        cp16(sb + oA0,                 Ah + ga0);
        cp16(sb + oA1,                 Ah + ga1);
        cp16(sb + ARR_BYTES + oA0,     Al + ga0);
        cp16(sb + ARR_BYTES + oA1,     Al + ga1);
        cp16(sb + 2 * ARR_BYTES + oA0, Bh + gb0);
        cp16(sb + 2 * ARR_BYTES + oA1, Bh + gb1);
        cp16(sb + 3 * ARR_BYTES + oA0, Bl + gb0);
        cp16(sb + 3 * ARR_BYTES + oA1, Bl + gb1);
    };

    const int ntiles = K / 32;
    issue(0, 0);
    asm volatile("cp.async.commit_group;");

    for (int t = 0; t < ntiles; t++) {
        if (t + 1 < ntiles) issue((t + 1) * 32, (t + 1) & 1);
        asm volatile("cp.async.commit_group;");
        asm volatile("cp.async.wait_group 1;");
        __syncthreads();

        const uint32_t stg = sbase + (uint32_t)(t & 1) * STG_BYTES;

#pragma unroll
        for (int ks = 0; ks < 2; ks++) {
            const uint32_t kbB = ks * 32;   // 8 u32 = 32 bytes
            uint32_t ah[4][4], al[4][4], bh[4][2], bl[4][2];
#pragma unroll
            for (int mi = 0; mi < 4; mi++) {
                ldmx4(ah[mi][0], ah[mi][1], ah[mi][2], ah[mi][3],
                      stg + offA[mi] + kbB);
                ldmx4(al[mi][0], al[mi][1], al[mi][2], al[mi][3],
                      stg + ARR_BYTES + offA[mi] + kbB);
            }
#pragma unroll
            for (int ni2 = 0; ni2 < 2; ni2++) {
                uint32_t x0, x1, x2, x3;
                ldmx4(x0, x1, x2, x3, stg + 2 * ARR_BYTES + offB[ni2] + kbB);
                bh[2 * ni2][0] = x0; bh[2 * ni2][1] = x1;
                bh[2 * ni2 + 1][0] = x2; bh[2 * ni2 + 1][1] = x3;
                ldmx4(x0, x1, x2, x3, stg + 3 * ARR_BYTES + offB[ni2] + kbB);
                bl[2 * ni2][0] = x0; bl[2 * ni2][1] = x1;
                bl[2 * ni2 + 1][0] = x2; bl[2 * ni2 + 1][1] = x3;
            }
#pragma unroll
            for (int mi = 0; mi < 4; mi++)
#pragma unroll
                for (int ni = 0; ni < 4; ni++) {
                    MMA_BF16(acc[mi][ni], ah[mi], bh[ni]);
                    MMA_BF16(acc[mi][ni], ah[mi], bl[ni]);
                    MMA_BF16(acc[mi][ni], al[mi], bh[ni]);
                }
        }
        __syncthreads();
    }

#pragma unroll
    for (int mi = 0; mi < 4; mi++)
#pragma unroll
        for (int ni = 0; ni < 4; ni++) {
            const int r = bm + wm * 64 + mi * 16 + g;
            const int c = bn + wn * 32 + ni * 8 + tg * 2;
            const float b0 = bias[c], b1 = bias[c + 1];
            C[(size_t)r * N + c]           = acc[mi][ni][0] + b0;
            C[(size_t)r * N + c + 1]       = acc[mi][ni][1] + b1;
            C[(size_t)(r + 8) * N + c]     = acc[mi][ni][2] + b0;
            C[(size_t)(r + 8) * N + c + 1] = acc[mi][ni][3] + b1;
        }
}

// ---------------------------------------------------------------------------
// Fused fp32 RMSNorm + 3-axis RoPE + scale + bf16 hi/lo split.
// ---------------------------------------------------------------------------
__global__ __launch_bounds__(256)
void norm_rope_split(const float* __restrict__ buf, const float* __restrict__ g,
                     const float* __restrict__ freqs,
                     const int* __restrict__ grid_sizes,
                     __nv_bfloat16* __restrict__ oh, __nv_bfloat16* __restrict__ ol,
                     float scale) {
    __shared__ float red[256];
    __shared__ float s_rn;
    const int row = blockIdx.x;
    const int tid = threadIdx.x;
    const float* rp = buf + (size_t)row * DIM;

    float ss = 0.f;
    for (int i = tid; i < DIM; i += 256) { float v = rp[i]; ss += v * v; }
    red[tid] = ss;
    __syncthreads();
#pragma unroll
    for (int st = 128; st > 0; st >>= 1) {
        if (tid < st) red[tid] += red[tid + st];
        __syncthreads();
    }
    if (tid == 0) s_rn = rsqrtf(red[0] / (float)DIM + 1e-6f);
    __syncthreads();
    const float rn = s_rn;

    const int gh = grid_sizes[1];
    const int gw = grid_sizes[2];
    const int fi = row / (gh * gw);
    const int hi = (row % (gh * gw)) / gw;
    const int wi = row % gw;

    for (int p = tid; p < DIM / 2; p += 256) {
        const int c = p & 63;
        const int pos = (c < 22) ? fi : ((c < 43) ? hi : wi);
        const float theta = freqs[pos * 64 + c];
        float sn, cs;
        sincosf(theta, &sn, &cs);
        const int idx = (p >> 6) * HDIM + 2 * c;
        const float xr = rp[idx]     * rn * g[idx];
        const float xi = rp[idx + 1] * rn * g[idx + 1];
        const float y0 = (xr * cs - xi * sn) * scale;
        const float y1 = (xr * sn + xi * cs) * scale;
        uint2 p2 = split2(y0, y1);
        *(uint32_t*)(oh + (size_t)row * DIM + idx) = p2.x;
        *(uint32_t*)(ol + (size_t)row * DIM + idx) = p2.y;
    }
}

// ---------------------------------------------------------------------------
// Tensor-core flash attention, bf16x3, ldmatrix fragments.
// BQ=64, BK=64, D=128. 128 threads = 4 warps; warp w owns q-rows [16w,16w+16).
// ---------------------------------------------------------------------------
#define QSTR 68   // u32 stride for Q/K smem rows (64 data + 4 pad)
#define VSTR 36   // u32 stride for V^T rows (32 data + 4 pad; conflict-free ldmatrix)

__global__ __launch_bounds__(128, 2)
void flash_mma(const __nv_bfloat16* __restrict__ Qh, const __nv_bfloat16* __restrict__ Ql,
               const __nv_bfloat16* __restrict__ Kh, const __nv_bfloat16* __restrict__ Kl,
               const __nv_bfloat16* __restrict__ Vh, const __nv_bfloat16* __restrict__ Vl,
               const int* __restrict__ seq_lens,
               __nv_bfloat16* __restrict__ Oh, __nv_bfloat16* __restrict__ Ol) {
    extern __shared__ uint32_t sm[];
    uint32_t* sQh = sm;
    uint32_t* sQl = sQh + 64 * QSTR;
    uint32_t* sKh = sQl + 64 * QSTR;
    uint32_t* sKl = sKh + 64 * QSTR;
    uint32_t* sVh = sKl + 64 * QSTR;          // [128][VSTR] (V transposed)
    uint32_t* sVl = sVh + 128 * VSTR;

    const uint32_t smbase = (uint32_t)__cvta_generic_to_shared(sm);
    const uint32_t bQh = smbase;
    const uint32_t bQl = bQh + 64 * QSTR * 4;
    const uint32_t bKh = bQl + 64 * QSTR * 4;
    const uint32_t bKl = bKh + 64 * QSTR * 4;
    const uint32_t bVh = bKl + 64 * QSTR * 4;
    const uint32_t bVl = bVh + 128 * VSTR * 4;

    const int head = blockIdx.y;
    const int q0 = blockIdx.x * 64;
    const int tid = threadIdx.x;
    const int w = tid >> 5, lane = tid & 31;
    const int g = lane >> 2, tg = lane & 3;
    const int m0 = w * 16;
    const int seqlen = seq_lens[0];
    const int GROW = DIM / 2;

    // ldmatrix byte offsets
    const uint32_t offQ = ((m0 + (lane & 15)) * QSTR + ((lane >> 4) << 2)) * 4;
    uint32_t offK[4], offV[8];
#pragma unroll
    for (int j2 = 0; j2 < 4; j2++)
        offK[j2] = ((16 * j2 + (lane & 7) + ((lane >> 4) << 3)) * QSTR +
                    (((lane >> 3) & 1) << 2)) * 4;
#pragma unroll
    for (int n2 = 0; n2 < 8; n2++)
        offV[n2] = ((16 * n2 + (lane & 7) + ((lane >> 4) << 3)) * VSTR +
                    (((lane >> 3) & 1) << 2)) * 4;

    {
        const uint32_t* gQh = (const uint32_t*)(Qh + (size_t)q0 * DIM + head * HDIM);
        const uint32_t* gQl = (const uint32_t*)(Ql + (size_t)q0 * DIM + head * HDIM);
        for (int i = tid; i < 64 * 64; i += 128) {
            const int r = i >> 6, c = i & 63;
            sQh[r * QSTR + c] = gQh[(size_t)r * GROW + c];
            sQl[r * QSTR + c] = gQl[(size_t)r * GROW + c];
        }
    }

    float m[2] = {-1e30f, -1e30f}, l[2] = {0.f, 0.f};
    float o[16][4];
#pragma unroll
    for (int n = 0; n < 16; n++)
#pragma unroll
        for (int r = 0; r < 4; r++) o[n][r] = 0.f;

    for (int k0 = 0; k0 < SEQ; k0 += 64) {
        if (k0 >= seqlen) break;
        __syncthreads();
        {
            const uint32_t* gKh = (const uint32_t*)(Kh + (size_t)k0 * DIM + head * HDIM);
            const uint32_t* gKl = (const uint32_t*)(Kl + (size_t)k0 * DIM + head * HDIM);
            for (int i = tid; i < 64 * 64; i += 128) {
                const int r = i >> 6, c = i & 63;
                sKh[r * QSTR + c] = gKh[(size_t)r * GROW + c];
                sKl[r * QSTR + c] = gKl[(size_t)r * GROW + c];
            }
        }
        {
            const uint32_t* gVh = (const uint32_t*)(Vh + (size_t)k0 * DIM + head * HDIM);
            const uint32_t* gVl = (const uint32_t*)(Vl + (size_t)k0 * DIM + head * HDIM);
            __nv_bfloat16* tVh = (__nv_bfloat16*)sVh;
            __nv_bfloat16* tVl = (__nv_bfloat16*)sVl;
            for (int i = tid; i < 64 * 64; i += 128) {
                const int r = i >> 6, du = i & 63;
                uint32_t vh = gVh[(size_t)r * GROW + du];
                uint32_t vl = gVl[(size_t)r * GROW + du];
                __nv_bfloat162 vh2 = *reinterpret_cast<__nv_bfloat162*>(&vh);
                __nv_bfloat162 vl2 = *reinterpret_cast<__nv_bfloat162*>(&vl);
                tVh[(2 * du)     * (2 * VSTR) + r] = vh2.x;
                tVh[(2 * du + 1) * (2 * VSTR) + r] = vh2.y;
                tVl[(2 * du)     * (2 * VSTR) + r] = vl2.x;
                tVl[(2 * du + 1) * (2 * VSTR) + r] = vl2.y;
            }
        }
        __syncthreads();

        // ---- scores S = Q K^T (bf16x3, ldmatrix fragments) ----
        float s[8][4];
#pragma unroll
        for (int j = 0; j < 8; j++)
#pragma unroll
            for (int r = 0; r < 4; r++) s[j][r] = 0.f;

#pragma unroll
        for (int ks = 0; ks < 8; ks++) {
            const uint32_t kbB = ks * 32;
            uint32_t ah[4], al[4];
            ldmx4(ah[0], ah[1], ah[2], ah[3], bQh + offQ + kbB);
            ldmx4(al[0], al[1], al[2], al[3], bQl + offQ + kbB);
#pragma unroll
            for (int j2 = 0; j2 < 4; j2++) {
                uint32_t x0, x1, x2, x3, y0, y1, y2, y3;
                ldmx4(x0, x1, x2, x3, bKh + offK[j2] + kbB);
                ldmx4(y0, y1, y2, y3, bKl + offK[j2] + kbB);
                uint32_t bh0[2] = {x0, x1}, bh1[2] = {x2, x3};
                uint32_t bl0[2] = {y0, y1}, bl1[2] = {y2, y3};
                MMA_BF16(s[2 * j2], ah, bh0);
                MMA_BF16(s[2 * j2], ah, bl0);
                MMA_BF16(s[2 * j2], al, bh0);
                MMA_BF16(s[2 * j2 + 1], ah, bh1);
                MMA_BF16(s[2 * j2 + 1], ah, bl1);
                MMA_BF16(s[2 * j2 + 1], al, bh1);
            }
        }

        // ---- online softmax (rows m0+g and m0+g+8, warp-local) ----
        const int kv = seqlen - k0;
        float mx0 = -1e30f, mx1 = -1e30f;
#pragma unroll
        for (int j = 0; j < 8; j++) {
            const int c0 = 8 * j + 2 * tg, c1 = c0 + 1;
            if (c0 >= kv) { s[j][0] = -1e30f; s[j][2] = -1e30f; }
            if (c1 >= kv) { s[j][1] = -1e30f; s[j][3] = -1e30f; }
            mx0 = fmaxf(mx0, fmaxf(s[j][0], s[j][1]));
            mx1 = fmaxf(mx1, fmaxf(s[j][2], s[j][3]));
        }
        mx0 = fmaxf(mx0, __shfl_xor_sync(0xffffffff, mx0, 1));
        mx0 = fmaxf(mx0, __shfl_xor_sync(0xffffffff, mx0, 2));
        mx1 = fmaxf(mx1, __shfl_xor_sync(0xffffffff, mx1, 1));
        mx1 = fmaxf(mx1, __shfl_xor_sync(0xffffffff, mx1, 2));
        const float mn0 = fmaxf(m[0], mx0);
        const float mn1 = fmaxf(m[1], mx1);
        const float a0 = __expf(m[0] - mn0);
        const float a1 = __expf(m[1] - mn1);
        m[0] = mn0; m[1] = mn1;

        float sum0 = 0.f, sum1 = 0.f;
#pragma unroll
        for (int j = 0; j < 8; j++) {
            s[j][0] = __expf(s[j][0] - mn0);
            s[j][1] = __expf(s[j][1] - mn0);
            s[j][2] = __expf(s[j][2] - mn1);
            s[j][3] = __expf(s[j][3] - mn1);
            sum0 += s[j][0] + s[j][1];
            sum1 += s[j][2] + s[j][3];
        }
        sum0 += __shfl_xor_sync(0xffffffff, sum0, 1);
        sum0 += __shfl_xor_sync(0xffffffff, sum0, 2);
        sum1 += __shfl_xor_sync(0xffffffff, sum1, 1);
        sum1 += __shfl_xor_sync(0xffffffff, sum1, 2);
        l[0] = l[0] * a0 + sum0;
        l[1] = l[1] * a1 + sum1;

#pragma unroll
        for (int n = 0; n < 16; n++) {
            o[n][0] *= a0; o[n][1] *= a0;
            o[n][2] *= a1; o[n][3] *= a1;
        }

        // ---- O += P V (bf16x3; ldmatrix V fragments) ----
#pragma unroll
        for (int kp = 0; kp < 4; kp++) {
            const uint32_t kpB = kp * 32;
            uint32_t ph[4], pl[4];
            const int j0 = 2 * kp, j1 = 2 * kp + 1;
            uint2 t;
            t = split2(s[j0][0], s[j0][1]); ph[0] = t.x; pl[0] = t.y;
            t = split2(s[j0][2], s[j0][3]); ph[1] = t.x; pl[1] = t.y;
            t = split2(s[j1][0], s[j1][1]); ph[2] = t.x; pl[2] = t.y;
            t = split2(s[j1][2], s[j1][3]); ph[3] = t.x; pl[3] = t.y;
#pragma unroll
            for (int n2 = 0; n2 < 8; n2++) {
                uint32_t x0, x1, x2, x3, y0, y1, y2, y3;
                ldmx4(x0, x1, x2, x3, bVh + offV[n2] + kpB);
                ldmx4(y0, y1, y2, y3, bVl + offV[n2] + kpB);
                uint32_t vh0[2] = {x0, x1}, vh1[2] = {x2, x3};
                uint32_t vl0[2] = {y0, y1}, vl1[2] = {y2, y3};
                MMA_BF16(o[2 * n2], ph, vh0);
                MMA_BF16(o[2 * n2], ph, vl0);
                MMA_BF16(o[2 * n2], pl, vh0);
                MMA_BF16(o[2 * n2 + 1], ph, vh1);
                MMA_BF16(o[2 * n2 + 1], ph, vl1);
                MMA_BF16(o[2 * n2 + 1], pl, vh1);
            }
        }
    }

    const float inv0 = 1.f / l[0];
    const float inv1 = 1.f / l[1];
    const int r0 = q0 + m0 + g;
    const int r1 = r0 + 8;
    uint32_t* oHh = (uint32_t*)(Oh);
    uint32_t* oLl = (uint32_t*)(Ol);
#pragma unroll
    for (int n = 0; n < 16; n++) {
        const int col = head * HDIM + 8 * n + 2 * tg;
        uint2 p0 = split2(o[n][0] * inv0, o[n][1] * inv0);
        oHh[(size_t)r0 * GROW + col / 2] = p0.x;
        oLl[(size_t)r0 * GROW + col / 2] = p0.y;
        uint2 p1 = split2(o[n][2] * inv1, o[n][3] * inv1);
        oHh[(size_t)r1 * GROW + col / 2] = p1.x;
        oLl[(size_t)r1 * GROW + col / 2] = p1.y;
    }
}

// ---------------------------------------------------------------------------
// Launch
// ---------------------------------------------------------------------------
extern "C" void kernel_launch(void* const* d_in, const int* in_sizes, int n_in,
                              void* d_out, int out_size) {
    const float* x         = (const float*)d_in[0];
    const int*   seq_lens  = (const int*)  d_in[1];
    const int*   grid_sz   = (const int*)  d_in[2];
    const float* freqs     = (const float*)d_in[3];
    const float* wq        = (const float*)d_in[4];
    const float* bq        = (const float*)d_in[5];
    const float* wk        = (const float*)d_in[6];
    const float* bk        = (const float*)d_in[7];
    const float* wv        = (const float*)d_in[8];
    const float* bv        = (const float*)d_in[9];
    const float* wo        = (const float*)d_in[10];
    const float* bo        = (const float*)d_in[11];
    const float* gq        = (const float*)d_in[12];
    const float* gk        = (const float*)d_in[13];
    float* out = (float*)d_out;

    float *q, *k, *v;
    cudaGetSymbolAddress((void**)&q, g_q);
    cudaGetSymbolAddress((void**)&k, g_k);
    cudaGetSymbolAddress((void**)&v, g_v);

    __nv_bfloat16 *xh, *xl, *ah, *al, *qh, *ql, *kh, *kl, *vh, *vl;
    __nv_bfloat16 *wqh, *wql, *wkh, *wkl, *wvh, *wvl, *woh, *wol;
    cudaGetSymbolAddress((void**)&xh,  g_xh);  cudaGetSymbolAddress((void**)&xl,  g_xl);
    cudaGetSymbolAddress((void**)&ah,  g_ah);  cudaGetSymbolAddress((void**)&al,  g_al);
    cudaGetSymbolAddress((void**)&qh,  g_qh);  cudaGetSymbolAddress((void**)&ql,  g_ql);
    cudaGetSymbolAddress((void**)&kh,  g_kh);  cudaGetSymbolAddress((void**)&kl,  g_kl);
    cudaGetSymbolAddress((void**)&vh,  g_vh);  cudaGetSymbolAddress((void**)&vl,  g_vl);
    cudaGetSymbolAddress((void**)&wqh, g_wqh); cudaGetSymbolAddress((void**)&wql, g_wql);
    cudaGetSymbolAddress((void**)&wkh, g_wkh); cudaGetSymbolAddress((void**)&wkl, g_wkl);
    cudaGetSymbolAddress((void**)&wvh, g_wvh); cudaGetSymbolAddress((void**)&wvl, g_wvl);
    cudaGetSymbolAddress((void**)&woh, g_woh); cudaGetSymbolAddress((void**)&wol, g_wol);

    const int nX = SEQ * DIM, nW = DIM * DIM;
    split_f32<<<nX / 1024, 256>>>(x,  xh,  xl,  nX);
    split_f32<<<nW / 1024, 256>>>(wq, wqh, wql, nW);
    split_f32<<<nW / 1024, 256>>>(wk, wkh, wkl, nW);
    split_f32<<<nW / 1024, 256>>>(wv, wvh, wvl, nW);
    split_f32<<<nW / 1024, 256>>>(wo, woh, wol, nW);

    const int gemm_smem = 2 * STG_BYTES;   // 81920 bytes
    cudaFuncSetAttribute(gemm_bf16x3_pipe,
                         cudaFuncAttributeMaxDynamicSharedMemorySize, gemm_smem);

    GemmBatch qkv;
    qkv.Bh[0] = wqh; qkv.Bl[0] = wql; qkv.bias[0] = bq; qkv.C[0] = q;
    qkv.Bh[1] = wkh; qkv.Bl[1] = wkl; qkv.bias[1] = bk; qkv.C[1] = k;
    qkv.Bh[2] = wvh; qkv.Bl[2] = wvl; qkv.bias[2] = bv; qkv.C[2] = v;
    gemm_bf16x3_pipe<<<dim3(DIM / 128, SEQ / 128, 3), 256, gemm_smem>>>(
        xh, xl, qkv, SEQ, DIM, DIM);

    const float scale = 0.08838834764831845f;   // 1/sqrt(128)
    norm_rope_split<<<SEQ, 256>>>(q, gq, freqs, grid_sz, qh, ql, scale);
    norm_rope_split<<<SEQ, 256>>>(k, gk, freqs, grid_sz, kh, kl, 1.0f);
    split_f32<<<nX / 1024, 256>>>(v, vh, vl, nX);

    const size_t fl_smem = (size_t)(4 * 64 * QSTR + 2 * 128 * VSTR) * sizeof(uint32_t);
    cudaFuncSetAttribute(flash_mma, cudaFuncAttributeMaxDynamicSharedMemorySize, (int)fl_smem);
    flash_mma<<<dim3(SEQ / 64, NHEADS), 128, fl_smem>>>(qh, ql, kh, kl, vh, vl,
                                                        seq_lens, ah, al);

    GemmBatch ob;
    ob.Bh[0] = woh; ob.Bl[0] = wol; ob.bias[0] = bo; ob.C[0] = out;
    ob.Bh[1] = woh; ob.Bl[1] = wol; ob.bias[1] = bo; ob.C[1] = out;
    ob.Bh[2] = woh; ob.Bl[2] = wol; ob.bias[2] = bo; ob.C[2] = out;
    gemm_bf16x3_pipe<<<dim3(DIM / 128, SEQ / 128, 1), 256, gemm_smem>>>(
        ah, al, ob, SEQ, DIM, DIM);
}